// round 2
// baseline (speedup 1.0000x reference)
#include <cuda_runtime.h>
#include <math.h>

#define NH 8
#define TS 128
#define DH 64
#define DM 512

// ---------------- scratch (static device memory; no allocations) ----------------
__device__ float g_k1[2*NH*TS*DH];
__device__ float g_k2[2*NH*TS*DH];
__device__ float g_q [2*NH*TS*DH];
__device__ float g_va[2*NH*TS*DH];
__device__ float g_vb[2*NH*TS*DH];
__device__ float g_rowA[2*NH*TS*TS];
__device__ float g_colB[2*NH*TS*TS];
__device__ float g_den [2*NH*TS];
__device__ float g_z  [2*NH*TS*DH];

// Fast exp: scores are tiny (|x| << 1); Taylor deg-8 on |x|<=0.9 (rel err ~1e-6),
// exact expf fallback otherwise. Keeps exp off the MUFU pipe (which would cost ~40us).
__device__ __forceinline__ float fast_exp(float x) {
    if (fabsf(x) > 0.9f) return expf(x);
    float r = 1.f/40320.f;
    r = r*x + 1.f/5040.f;
    r = r*x + 1.f/720.f;
    r = r*x + 1.f/120.f;
    r = r*x + 1.f/24.f;
    r = r*x + 1.f/6.f;
    r = r*x + 0.5f;
    r = r*x + 1.f;
    r = r*x + 1.f;
    return r;
}

// ---------------- kernel 1: five projections  out[b,n,p,h] = x[b,p,:] @ W[n,:,h] + bias --------
// grid (10, 8, 2): blockIdx.x = proj*2 + ptile ; block computes [64p x 64h], K=512.
__global__ void proj_kernel(const float* __restrict__ x,
                            const float* __restrict__ Wk1, const float* __restrict__ Wk2,
                            const float* __restrict__ Wq,  const float* __restrict__ Wv12,
                            const float* __restrict__ bk1, const float* __restrict__ bk2,
                            const float* __restrict__ bq)
{
    __shared__ __align__(16) float xs[64*33];
    __shared__ __align__(16) float ws[32*68];
    int tid = threadIdx.x;
    int px = blockIdx.x;
    int n  = blockIdx.y;
    int b  = blockIdx.z;
    int proj = px >> 1;
    int p0 = (px & 1) * 64;

    const float* W; const float* bias; float* dst;
    if (proj == 0)      { W = Wk1 + n*DM*DH;            bias = bk1 + n*DH; dst = g_k1; }
    else if (proj == 1) { W = Wk2 + n*DM*DH;            bias = bk2 + n*DH; dst = g_k2; }
    else if (proj == 2) { W = Wq  + n*DM*DH;            bias = bq  + n*DH; dst = g_q;  }
    else if (proj == 3) { W = Wv12 + n*2*DM*DH;         bias = 0;          dst = g_va; }
    else                { W = Wv12 + n*2*DM*DH + DM*DH; bias = 0;          dst = g_vb; }

    const float* xb = x + b*TS*DM;
    int ty = tid >> 4, tx = tid & 15;
    float acc[4][4];
    #pragma unroll
    for (int p = 0; p < 4; p++)
        #pragma unroll
        for (int c = 0; c < 4; c++) acc[p][c] = 0.f;

    for (int k0 = 0; k0 < DM; k0 += 32) {
        #pragma unroll
        for (int r = 0; r < 8; r++) {
            int e = tid + r*256;
            int pp = e >> 5, kk = e & 31;
            xs[pp*33 + kk] = xb[(p0+pp)*DM + k0 + kk];
        }
        #pragma unroll
        for (int r = 0; r < 8; r++) {
            int e = tid + r*256;
            int kk = e >> 6, hh = e & 63;
            ws[kk*68 + hh] = W[(k0+kk)*DH + hh];
        }
        __syncthreads();
        #pragma unroll
        for (int k = 0; k < 32; k++) {
            float4 bv = *(const float4*)&ws[k*68 + tx*4];
            #pragma unroll
            for (int p = 0; p < 4; p++) {
                float a = xs[(ty*4+p)*33 + k];
                acc[p][0] += a*bv.x; acc[p][1] += a*bv.y;
                acc[p][2] += a*bv.z; acc[p][3] += a*bv.w;
            }
        }
        __syncthreads();
    }
    int bn = b*NH + n;
    #pragma unroll
    for (int p = 0; p < 4; p++) {
        int prow = p0 + ty*4 + p;
        float* o = dst + (bn*TS + prow)*DH + tx*4;
        #pragma unroll
        for (int c = 0; c < 4; c++) {
            float v = acc[p][c];
            if (bias) v += bias[tx*4 + c];
            o[c] = v;
        }
    }
}

// ---------------- kernel 2: per (b,n,q): E=exp(S/64) for s<t<q, rowA/colB/den ----------------
// grid (128, 8, 2), 256 threads, dynamic smem.
__global__ void attn_kernel()
{
    extern __shared__ __align__(16) float sm[];
    float* su  = sm;                 // 128 x 68 (u = q*k1), float4 stride 17
    float* sk2 = su + 128*68;        // 128 x 68
    float* sE  = sk2 + 128*68;       // 128 x 132 (float4 stride 33)
    float* sqv = sE + 128*132;       // 64
    float* srA = sqv + 64;           // 128

    int tid = threadIdx.x;
    int Q = blockIdx.x, n = blockIdx.y, b = blockIdx.z;
    int bn = b*NH + n;

    if (Q < 2) {                     // empty softmax -> all mass on sink -> z = 0
        if (tid < TS) {
            g_rowA[(bn*TS + Q)*TS + tid] = 0.f;
            g_colB[(bn*TS + Q)*TS + tid] = 0.f;
        }
        if (tid == 0) g_den[bn*TS + Q] = 0.f;
        return;
    }

    const float4* gq4 = (const float4*)(g_q + (bn*TS + Q)*DH);
    if (tid < 16) ((float4*)sqv)[tid] = gq4[tid];
    __syncthreads();

    const float4* gk14 = (const float4*)(g_k1 + bn*TS*DH);
    const float4* gk24 = (const float4*)(g_k2 + bn*TS*DH);
    float4* su4  = (float4*)su;
    float4* sk24 = (float4*)sk2;
    float4* sE4  = (float4*)sE;

    int nload = Q * 16;
    for (int e = tid; e < nload; e += 256) {
        int s = e >> 4, h4 = e & 15;
        float4 qv = ((float4*)sqv)[h4];
        float4 a = gk14[s*16 + h4];
        a.x *= qv.x; a.y *= qv.y; a.z *= qv.z; a.w *= qv.w;
        su4 [s*17 + h4] = a;
        sk24[s*17 + h4] = gk24[s*16 + h4];
    }
    float4 zz = make_float4(0.f, 0.f, 0.f, 0.f);
    for (int e = tid; e < 128*33; e += 256) sE4[e] = zz;
    __syncthreads();

    int T = (Q + 3) >> 2;
    int ntiles = T*(T+1)/2;
    const float inv = 1.f/64.f;

    for (int tile = tid; tile < ntiles; tile += 256) {
        // decode lower-triangular tile index (i <= j)
        int j = (int)((sqrtf(8.f*(float)tile + 1.f) - 1.f) * 0.5f);
        while ((j+1)*(j+2)/2 <= tile) j++;
        while (j*(j+1)/2 > tile) j--;
        int i = tile - j*(j+1)/2;

        const float4* ua = su4  + i*4*17;
        const float4* kb = sk24 + j*4*17;
        float acc[4][4];
        #pragma unroll
        for (int p = 0; p < 4; p++)
            #pragma unroll
            for (int r = 0; r < 4; r++) acc[p][r] = 0.f;

        #pragma unroll
        for (int h4 = 0; h4 < 16; h4++) {
            float4 av[4], bv[4];
            av[0] = ua[h4]; av[1] = ua[17+h4]; av[2] = ua[34+h4]; av[3] = ua[51+h4];
            bv[0] = kb[h4]; bv[1] = kb[17+h4]; bv[2] = kb[34+h4]; bv[3] = kb[51+h4];
            #pragma unroll
            for (int p = 0; p < 4; p++)
                #pragma unroll
                for (int r = 0; r < 4; r++)
                    acc[p][r] += av[p].x*bv[r].x + av[p].y*bv[r].y
                               + av[p].z*bv[r].z + av[p].w*bv[r].w;
        }
        int s0 = i*4, t0 = j*4;
        #pragma unroll
        for (int p = 0; p < 4; p++)
            #pragma unroll
            for (int r = 0; r < 4; r++) {
                int s = s0 + p, t = t0 + r;
                if (s < t && t < Q)
                    sE[s*132 + t] = fast_exp(acc[p][r] * inv);
            }
    }
    __syncthreads();

    if (tid < 128) {
        int s = tid;
        const float4* row = (const float4*)(sE + s*132);
        float sum = 0.f;
        #pragma unroll
        for (int w = 0; w < 32; w++) { float4 v = row[w]; sum += v.x + v.y + v.z + v.w; }
        srA[s] = sum;
        g_rowA[(bn*TS + Q)*TS + s] = sum;
    } else {
        int t = tid - 128;
        float sum = 0.f;
        #pragma unroll 8
        for (int s = 0; s < 128; s++) sum += sE[s*132 + t];
        g_colB[(bn*TS + Q)*TS + t] = sum;
    }
    __syncthreads();

    if (tid < 32) {
        float v = srA[tid] + srA[tid+32] + srA[tid+64] + srA[tid+96];
        #pragma unroll
        for (int o = 16; o > 0; o >>= 1) v += __shfl_down_sync(0xffffffffu, v, o);
        if (tid == 0) g_den[bn*TS + Q] = v;
    }
}

// ---------------- kernel 3: z[q,h] = (rowA.va + colB.vb)/den + b_V12 ----------------
// grid (4, 8, 2), 256 threads, dynamic smem.
__global__ void z_kernel(const float* __restrict__ bv12)
{
    extern __shared__ __align__(16) float sm[];
    float* sRA = sm;                 // 32 x 128
    float* sCB = sRA + 32*128;       // 32 x 128
    float* sva = sCB + 32*128;       // 128 x 68
    float* svb = sva + 128*68;       // 128 x 68
    int tid = threadIdx.x;
    int q0 = blockIdx.x * 32, n = blockIdx.y, b = blockIdx.z;
    int bn = b*NH + n;

    const float* gra = g_rowA + (bn*TS + q0)*TS;
    const float* gcb = g_colB + (bn*TS + q0)*TS;
    for (int e = tid; e < 32*128; e += 256) { sRA[e] = gra[e]; sCB[e] = gcb[e]; }

    const float4* gva4 = (const float4*)(g_va + bn*TS*DH);
    const float4* gvb4 = (const float4*)(g_vb + bn*TS*DH);
    float4* sva4 = (float4*)sva;
    float4* svb4 = (float4*)svb;
    for (int e = tid; e < 128*16; e += 256) {
        int s = e >> 4, h4 = e & 15;
        sva4[s*17 + h4] = gva4[e];
        svb4[s*17 + h4] = gvb4[e];
    }
    __syncthreads();

    int qi = tid >> 3;               // 0..31
    int hb = (tid & 7) * 2;          // float4-unit base: h = hb*4 .. hb*4+7
    float accA[8], accB[8];
    #pragma unroll
    for (int k = 0; k < 8; k++) { accA[k] = 0.f; accB[k] = 0.f; }

    const float* ra = sRA + qi*128;
    const float* cb = sCB + qi*128;
    #pragma unroll 4
    for (int s = 0; s < 128; s++) {
        float a = ra[s], c = cb[s];
        float4 v0 = sva4[s*17 + hb], v1 = sva4[s*17 + hb + 1];
        float4 w0 = svb4[s*17 + hb], w1 = svb4[s*17 + hb + 1];
        accA[0] += a*v0.x; accA[1] += a*v0.y; accA[2] += a*v0.z; accA[3] += a*v0.w;
        accA[4] += a*v1.x; accA[5] += a*v1.y; accA[6] += a*v1.z; accA[7] += a*v1.w;
        accB[0] += c*w0.x; accB[1] += c*w0.y; accB[2] += c*w0.z; accB[3] += c*w0.w;
        accB[4] += c*w1.x; accB[5] += c*w1.y; accB[6] += c*w1.z; accB[7] += c*w1.w;
    }
    int q = q0 + qi;
    float den = g_den[bn*TS + q];
    float* zo = g_z + (bn*TS + q)*DH + hb*4;
    const float* bv = bv12 + n*DH + hb*4;
    if (den > 0.f) {
        float r = 1.f / den;
        #pragma unroll
        for (int k = 0; k < 8; k++) zo[k] = (accA[k] + accB[k])*r + bv[k];
    } else {
        #pragma unroll
        for (int k = 0; k < 8; k++) zo[k] = 0.f;
    }
}

// ---------------- kernel 4: out[b,p,d] = sum_{n,h} z[b,n,p,h] * W_O[n,h,d] + b_O ----------------
// grid (4, 8, 2): [32p x 64d] tile per block.
__global__ void out_kernel(const float* __restrict__ Wo, const float* __restrict__ bo,
                           float* __restrict__ out)
{
    __shared__ __align__(16) float zs[32*65];
    __shared__ __align__(16) float ws[64*68];
    int tid = threadIdx.x;
    int p0 = blockIdx.x * 32, d0 = blockIdx.y * 64, b = blockIdx.z;
    int ty = tid >> 4, tx = tid & 15;
    float acc[2][4];
    #pragma unroll
    for (int r = 0; r < 2; r++)
        #pragma unroll
        for (int c = 0; c < 4; c++) acc[r][c] = 0.f;

    for (int n = 0; n < NH; n++) {
        #pragma unroll
        for (int r = 0; r < 8; r++) {
            int e = tid + r*256;
            int p = e >> 6, h = e & 63;
            zs[p*65 + h] = g_z[((b*NH + n)*TS + p0 + p)*DH + h];
        }
        #pragma unroll
        for (int r = 0; r < 16; r++) {
            int e = tid + r*256;
            int h = e >> 6, d = e & 63;
            ws[h*68 + d] = Wo[(n*DH + h)*DM + d0 + d];
        }
        __syncthreads();
        #pragma unroll
        for (int h = 0; h < 64; h++) {
            float4 w = *(const float4*)&ws[h*68 + tx*4];
            float a0 = zs[(ty*2)*65 + h];
            float a1 = zs[(ty*2+1)*65 + h];
            acc[0][0] += a0*w.x; acc[0][1] += a0*w.y; acc[0][2] += a0*w.z; acc[0][3] += a0*w.w;
            acc[1][0] += a1*w.x; acc[1][1] += a1*w.y; acc[1][2] += a1*w.z; acc[1][3] += a1*w.w;
        }
        __syncthreads();
    }
    #pragma unroll
    for (int r = 0; r < 2; r++) {
        int p = p0 + ty*2 + r;
        float* o = out + b*TS*DM + p*DM + d0 + tx*4;
        #pragma unroll
        for (int c = 0; c < 4; c++) o[c] = acc[r][c] + bo[d0 + tx*4 + c];
    }
}

// ---------------- launch ----------------
extern "C" void kernel_launch(void* const* d_in, const int* in_sizes, int n_in,
                              void* d_out, int out_size)
{
    const float* x    = (const float*)d_in[0];
    const float* Wk1  = (const float*)d_in[1];
    const float* Wk2  = (const float*)d_in[2];
    const float* Wq   = (const float*)d_in[3];
    const float* Wv12 = (const float*)d_in[4];
    const float* Wo   = (const float*)d_in[5];
    const float* bk1  = (const float*)d_in[6];
    const float* bk2  = (const float*)d_in[7];
    const float* bq   = (const float*)d_in[8];
    const float* bv12 = (const float*)d_in[9];
    const float* bo   = (const float*)d_in[10];
    float* out = (float*)d_out;

    proj_kernel<<<dim3(10, 8, 2), 256>>>(x, Wk1, Wk2, Wq, Wv12, bk1, bk2, bq);

    int smem2 = (128*68*2 + 128*132 + 64 + 128) * (int)sizeof(float);  // ~138.2 KB
    cudaFuncSetAttribute(attn_kernel, cudaFuncAttributeMaxDynamicSharedMemorySize, smem2);
    attn_kernel<<<dim3(128, 8, 2), 256, smem2>>>();

    int smem3 = (32*128*2 + 128*68*2) * (int)sizeof(float);            // 100 KB
    cudaFuncSetAttribute(z_kernel, cudaFuncAttributeMaxDynamicSharedMemorySize, smem3);
    z_kernel<<<dim3(4, 8, 2), 256, smem3>>>(bv12);

    out_kernel<<<dim3(4, 8, 2), 256>>>(Wo, bo, out);
}